// round 6
// baseline (speedup 1.0000x reference)
#include <cuda_runtime.h>
#include <cuda_bf16.h>
#include <cstdint>

// Problem constants (fixed by setup_inputs): T=128, N=2048, D=256, w=3
#define T_SNAP 128
#define N_NODE 2048
#define D_HID  256
#define WIN    3
#define ROWS   (T_SNAP * N_NODE)   // 262144

// Scratch (allocation-free rule: __device__ globals)
__device__ float g_score[ROWS];
__device__ float g_p[ROWS];
// Pre-packed W: g_Wb[(c*16 + k2)*256 + n] = bf16x2{ W[32c+2k2][n], W[32c+2k2+1][n] }
__device__ uint32_t g_Wb[8 * 16 * 256];   // 128 KB

// ---------------------------------------------------------------------------
__device__ __forceinline__ uint32_t pack_bf16(float lo, float hi) {
    __nv_bfloat162 h = __floats2bfloat162_rn(lo, hi);
    return *reinterpret_cast<uint32_t*>(&h);
}

__device__ __forceinline__ void mma_bf16(float* c, const uint32_t* a, const uint32_t* b) {
    asm volatile(
        "mma.sync.aligned.m16n8k16.row.col.f32.bf16.bf16.f32 "
        "{%0,%1,%2,%3}, {%4,%5,%6,%7}, {%8,%9}, {%0,%1,%2,%3};"
        : "+f"(c[0]), "+f"(c[1]), "+f"(c[2]), "+f"(c[3])
        : "r"(a[0]), "r"(a[1]), "r"(a[2]), "r"(a[3]), "r"(b[0]), "r"(b[1]));
}

__device__ __forceinline__ void cp_async16(uint32_t smem_dst, const void* gptr) {
    asm volatile("cp.async.cg.shared.global [%0], [%1], 16;"
                 :: "r"(smem_dst), "l"(gptr) : "memory");
}
__device__ __forceinline__ void cp_commit() {
    asm volatile("cp.async.commit_group;" ::: "memory");
}
__device__ __forceinline__ void cp_wait1() {
    asm volatile("cp.async.wait_group 1;" ::: "memory");
}
__device__ __forceinline__ void cp_wait0() {
    asm volatile("cp.async.wait_group 0;" ::: "memory");
}

// ---------------------------------------------------------------------------
// Kernel 0: pack W into bf16x2 chunk layout (one-shot, ~µs)
// ---------------------------------------------------------------------------
__global__ __launch_bounds__(256) void prep_w_kernel(const float* __restrict__ W)
{
    int idx = blockIdx.x * 256 + threadIdx.x;  // 0..32767
    int n  = idx & 255;
    int kk = idx >> 8;                         // global k-pair 0..127
    g_Wb[idx] = pack_bf16(W[(2 * kk) * D_HID + n], W[(2 * kk + 1) * D_HID + n]);
}

// ---------------------------------------------------------------------------
// Kernel 1 (mma.sync bf16, all-async depth-2 pipeline):
//   score[row] = proj . tanh( X[row,:] @ W )
// Block 256 threads = 8 warps, 2(M) x 4(N). Tile M=64, N=256, BK=32 x 8.
// Triple-buffered smem; A arrives raw f32 via cp.async (converted to bf16x2
// in the fragment path); B arrives pre-packed via cp.async from g_Wb.
// One commit group per chunk; wait_group 1 => distance-2 prefetch.
// ---------------------------------------------------------------------------
#define AS_STRIDE 40    // f32 per A row (32 data + 8 pad): conflict-free LDS.64 frags
#define BS_STRIDE 264   // u32 per B row (256 data + 8 pad): conflict-free frags
#define ASB (64 * AS_STRIDE * 4)        // 10240 B per A buffer
#define BSB (16 * BS_STRIDE * 4)        // 16896 B per B buffer
#define AS_OFF   0
#define BS_OFF   (3 * ASB)              // 30720
#define PROJ_OFF (BS_OFF + 3 * BSB)     // 81408
#define PART_OFF (PROJ_OFF + 1024)      // 82432
#define SMEM_TOTAL (PART_OFF + 1024)    // 83456

__global__ __launch_bounds__(256, 2) void score_kernel(
    const float* __restrict__ X,
    const float* __restrict__ proj)
{
    extern __shared__ char smem[];
    const int tid    = threadIdx.x;
    const int lane   = tid & 31;
    const int wid    = tid >> 5;
    const int warp_m = wid >> 2;
    const int warp_n = wid & 3;
    const int qid    = lane >> 2;
    const int qlane  = lane & 3;
    const int row0   = blockIdx.x * 64;

    float* sproj = (float*)(smem + PROJ_OFF);
    float* part  = (float*)(smem + PART_OFF);
    sproj[tid] = proj[tid];

    // Per-thread fixed staging coordinates
    const int bm0 = tid >> 3, bc0 = tid & 7;             // A seg 0 (row, 16B-col)
    const int bm1 = (tid + 256) >> 3, bc1 = (tid + 256) & 7;
    const uint32_t smem_base = (uint32_t)__cvta_generic_to_shared(smem);

    float acc[2][8][4];
    #pragma unroll
    for (int mt = 0; mt < 2; mt++)
        #pragma unroll
        for (int nt = 0; nt < 8; nt++)
            #pragma unroll
            for (int i = 0; i < 4; i++) acc[mt][nt][i] = 0.0f;

    // Stage chunk c into buffer bf
    auto stage = [&](int c, int bf) {
        // B: 4 x 16B per thread from g_Wb (L2-hot)
        #pragma unroll
        for (int i = 0; i < 4; i++) {
            int seg = tid + i * 256;
            int k2  = seg >> 6;
            int ng  = seg & 63;
            cp_async16(smem_base + BS_OFF + bf * BSB + (k2 * BS_STRIDE + ng * 4) * 4,
                       &g_Wb[(c * 16 + k2) * 256 + ng * 4]);
        }
        // A: 2 x 16B per thread, raw f32 rows (128B contiguous per row)
        cp_async16(smem_base + AS_OFF + bf * ASB + (bm0 * AS_STRIDE + bc0 * 4) * 4,
                   X + (row0 + bm0) * 256 + c * 32 + bc0 * 4);
        cp_async16(smem_base + AS_OFF + bf * ASB + (bm1 * AS_STRIDE + bc1 * 4) * 4,
                   X + (row0 + bm1) * 256 + c * 32 + bc1 * 4);
    };

    stage(0, 0); cp_commit();
    stage(1, 1); cp_commit();

    #pragma unroll 1
    for (int c = 0; c < 8; ++c) {
        if (c < 7) cp_wait1(); else cp_wait0();   // chunk c complete
        __syncthreads();                          // visible to all; prev compute done
        if (c + 2 < 8) { stage(c + 2, (c + 2) % 3); cp_commit(); }

        const int bf = c % 3;
        const float*    Ab = (const float*)(smem + AS_OFF + bf * ASB);
        const uint32_t* Bb = (const uint32_t*)(smem + BS_OFF + bf * BSB);

        #pragma unroll
        for (int ks = 0; ks < 2; ks++) {
            uint32_t a[2][4];
            #pragma unroll
            for (int mt = 0; mt < 2; mt++) {
                int r = warp_m * 32 + mt * 16 + qid;
                const float* pr  = Ab + r * AS_STRIDE + ks * 16 + 2 * qlane;
                const float* pr8 = pr + 8 * AS_STRIDE;
                float2 v0 = *reinterpret_cast<const float2*>(pr);
                float2 v1 = *reinterpret_cast<const float2*>(pr8);
                float2 v2 = *reinterpret_cast<const float2*>(pr + 8);
                float2 v3 = *reinterpret_cast<const float2*>(pr8 + 8);
                a[mt][0] = pack_bf16(v0.x, v0.y);
                a[mt][1] = pack_bf16(v1.x, v1.y);
                a[mt][2] = pack_bf16(v2.x, v2.y);
                a[mt][3] = pack_bf16(v3.x, v3.y);
            }
            const int k2b = ks * 8;
            uint32_t b[8][2];
            #pragma unroll
            for (int nt = 0; nt < 8; nt++) {
                int n = warp_n * 64 + nt * 8 + qid;
                b[nt][0] = Bb[(k2b + qlane)     * BS_STRIDE + n];
                b[nt][1] = Bb[(k2b + qlane + 4) * BS_STRIDE + n];
            }
            #pragma unroll
            for (int mt = 0; mt < 2; mt++)
                #pragma unroll
                for (int nt = 0; nt < 8; nt++)
                    mma_bf16(acc[mt][nt], a[mt], b[nt]);
        }
    }

    // Fused epilogue: per-row sum of tanh(u)*proj over this warp's 64 cols.
    float psum[2][2];
    psum[0][0] = psum[0][1] = psum[1][0] = psum[1][1] = 0.0f;
    #pragma unroll
    for (int mt = 0; mt < 2; mt++)
        #pragma unroll
        for (int nt = 0; nt < 8; nt++) {
            int cb = warp_n * 64 + nt * 8 + 2 * qlane;
            float p0 = sproj[cb], p1 = sproj[cb + 1];
            psum[mt][0] += tanhf(acc[mt][nt][0]) * p0 + tanhf(acc[mt][nt][1]) * p1;
            psum[mt][1] += tanhf(acc[mt][nt][2]) * p0 + tanhf(acc[mt][nt][3]) * p1;
        }
    #pragma unroll
    for (int off = 1; off < 4; off <<= 1) {
        #pragma unroll
        for (int mt = 0; mt < 2; mt++) {
            psum[mt][0] += __shfl_xor_sync(0xffffffffu, psum[mt][0], off);
            psum[mt][1] += __shfl_xor_sync(0xffffffffu, psum[mt][1], off);
        }
    }
    __syncthreads();
    if (qlane == 0) {
        #pragma unroll
        for (int mt = 0; mt < 2; mt++) {
            part[warp_n * 64 + warp_m * 32 + mt * 16 + qid]     = psum[mt][0];
            part[warp_n * 64 + warp_m * 32 + mt * 16 + qid + 8] = psum[mt][1];
        }
    }
    __syncthreads();
    if (tid < 64)
        g_score[row0 + tid] =
            part[tid] + part[64 + tid] + part[128 + tid] + part[192 + tid];
}

// ---------------------------------------------------------------------------
// Kernel 2: p[j,:] = softmax over N of score[j,:]   (one block per row j)
// ---------------------------------------------------------------------------
__global__ __launch_bounds__(256) void softmax_kernel()
{
    __shared__ float red_max[8];
    __shared__ float red_sum[8];
    const int j   = blockIdx.x;
    const int tid = threadIdx.x;
    const float* row = g_score + j * N_NODE;

    float v[8];
    float m = -1e30f;
    #pragma unroll
    for (int i = 0; i < 8; i++) {
        v[i] = row[tid + i * 256];
        m = fmaxf(m, v[i]);
    }
    #pragma unroll
    for (int off = 16; off > 0; off >>= 1)
        m = fmaxf(m, __shfl_xor_sync(0xffffffffu, m, off));
    if ((tid & 31) == 0) red_max[tid >> 5] = m;
    __syncthreads();
    float bm = red_max[0];
    #pragma unroll
    for (int wq = 1; wq < 8; wq++) bm = fmaxf(bm, red_max[wq]);

    float s = 0.0f;
    #pragma unroll
    for (int i = 0; i < 8; i++) {
        v[i] = expf(v[i] - bm);
        s += v[i];
    }
    #pragma unroll
    for (int off = 16; off > 0; off >>= 1)
        s += __shfl_xor_sync(0xffffffffu, s, off);
    if ((tid & 31) == 0) red_sum[tid >> 5] = s;
    __syncthreads();
    float bs = 0.0f;
    #pragma unroll
    for (int wq = 0; wq < 8; wq++) bs += red_sum[wq];
    float inv = 1.0f / bs;

    #pragma unroll
    for (int i = 0; i < 8; i++)
        g_p[j * N_NODE + tid + i * 256] = v[i] * inv;
}

// ---------------------------------------------------------------------------
// Kernel 3: out. Blocks are snapshot-aligned (uniform branch); each thread
// handles one (i,n) and 4 float4 d-chunks -> p loads amortized, 12 LDGs in
// flight. Block = 16 nodes x 16 threads.
// ---------------------------------------------------------------------------
__global__ __launch_bounds__(256) void out_kernel(
    const float4* __restrict__ X4,
    float4* __restrict__ out4)
{
    const int STRIDE_T = N_NODE * 64;           // float4 per snapshot
    const int i  = blockIdx.x >> 7;             // snapshot 0..127
    const int n  = ((blockIdx.x & 127) << 4) + (threadIdx.x >> 4);
    const int dp = threadIdx.x & 15;
    const int base = (i * N_NODE + n) * 64;

    if (i < WIN) {
        #pragma unroll
        for (int q = 0; q < 4; q++)
            out4[base + dp + q * 16] = X4[base + dp + q * 16];
    } else {
        const int pb = (i - 3) * N_NODE + n;
        const float p0 = g_p[pb];
        const float p1 = g_p[pb + N_NODE];
        const float p2 = g_p[pb + 2 * N_NODE];
        #pragma unroll
        for (int q = 0; q < 4; q++) {
            int d = base + dp + q * 16;
            float4 a = X4[d - 3 * STRIDE_T];
            float4 b = X4[d - 2 * STRIDE_T];
            float4 c = X4[d - 1 * STRIDE_T];
            float4 o;
            o.x = p0 * a.x + p1 * b.x + p2 * c.x;
            o.y = p0 * a.y + p1 * b.y + p2 * c.y;
            o.z = p0 * a.z + p1 * b.z + p2 * c.z;
            o.w = p0 * a.w + p1 * b.w + p2 * c.w;
            out4[d] = o;
        }
    }
}

// ---------------------------------------------------------------------------
extern "C" void kernel_launch(void* const* d_in, const int* in_sizes, int n_in,
                              void* d_out, int out_size)
{
    const float* X    = (const float*)d_in[0];  // (128, 2048, 256)
    const float* W    = (const float*)d_in[1];  // (256, 256)
    const float* proj = (const float*)d_in[2];  // (256, 1)
    float* out        = (float*)d_out;

    cudaFuncSetAttribute(score_kernel,
                         cudaFuncAttributeMaxDynamicSharedMemorySize, SMEM_TOTAL);

    prep_w_kernel<<<128, 256>>>(W);
    score_kernel<<<ROWS / 64, 256, SMEM_TOTAL>>>(X, proj);
    softmax_kernel<<<T_SNAP, 256>>>();
    out_kernel<<<T_SNAP * 128, 256>>>((const float4*)X, (float4*)out);
}